// round 14
// baseline (speedup 1.0000x reference)
#include <cuda_runtime.h>
#include <cstdint>

#define NTOK  64
#define HID   2048
#define INTER 1408
#define NEXP  32
#define TOPK  4
#define NASS  (NTOK*TOPK)

typedef unsigned long long ull;

// ---------------- scratch ----------------
__device__ int   g_cnt[NEXP];
__device__ int   g_off[NEXP];
__device__ int   g_tok[NASS];
__device__ float g_wass[NASS];
__device__ float g_mixed[(size_t)NASS*INTER];

// ---------------- f32x2 packed FMA ----------------
__device__ __forceinline__ void fma2(ull &a, ull b, ull c) {
    asm("fma.rn.f32x2 %0, %1, %2, %0;" : "+l"(a) : "l"(b), "l"(c));
}
__device__ __forceinline__ float hsum(ull a) {
    float lo = __uint_as_float((unsigned)a);
    float hi = __uint_as_float((unsigned)(a >> 32));
    float s = lo + hi;
    #pragma unroll
    for (int o = 16; o > 0; o >>= 1) s += __shfl_xor_sync(0xffffffffu, s, o);
    return s;
}

// ---------------- cp.async helpers ----------------
__device__ __forceinline__ void cpa16(uint32_t dst, const float* src) {
    asm volatile("cp.async.cg.shared.global [%0], [%1], 16;" :: "r"(dst), "l"(src));
}
__device__ __forceinline__ void cpa_commit() { asm volatile("cp.async.commit_group;"); }
__device__ __forceinline__ void cpa_wait2()  { asm volatile("cp.async.wait_group 2;"); }

// ---------------- 1) routing: ballot-ranked, 256 threads ----------------
__global__ void route_k(const float* __restrict__ logits) {
    __shared__ int   s_ids[NTOK][TOPK];
    __shared__ float s_w  [NTOK][TOPK];
    __shared__ int   s_wcnt[8][NEXP];
    __shared__ int   s_cnt[NEXP];
    __shared__ int   s_off[NEXP];
    int tid = threadIdx.x;

    ((int*)s_wcnt)[tid] = 0;

    if (tid < NTOK) {
        int t = tid;
        float v[NEXP];
        #pragma unroll
        for (int e = 0; e < NEXP; e++) v[e] = logits[t*NEXP + e];

        int ids[TOPK]; float vals[TOPK];
        #pragma unroll
        for (int j = 0; j < TOPK; j++) {
            int bi = 0; float bv = -1e30f;
            #pragma unroll
            for (int e = 0; e < NEXP; e++) if (v[e] > bv) { bv = v[e]; bi = e; }
            ids[j] = bi; vals[j] = bv; v[bi] = -1e30f;
        }
        float m = vals[0], s = 0.f, w[TOPK];
        #pragma unroll
        for (int j = 0; j < TOPK; j++) { w[j] = __expf(vals[j] - m); s += w[j]; }
        float inv = 1.f / s;
        #pragma unroll
        for (int j = 0; j < TOPK; j++) { s_ids[t][j] = ids[j]; s_w[t][j] = w[j] * inv; }
    }
    __syncthreads();

    int a = tid, t = a >> 2, j = a & 3;
    int e = s_ids[t][j];
    int warp = a >> 5, lane = a & 31;
    unsigned mask = __match_any_sync(0xffffffffu, e);
    int rin = __popc(mask & ((1u << lane) - 1u));
    if (rin == 0) s_wcnt[warp][e] = __popc(mask);
    __syncthreads();

    if (tid < NEXP) {
        int c = 0;
        #pragma unroll
        for (int w = 0; w < 8; w++) c += s_wcnt[w][tid];
        s_cnt[tid] = c; g_cnt[tid] = c;
    }
    __syncthreads();
    if (tid < NEXP) {
        int o = 0;
        for (int ee = 0; ee < tid; ee++) o += s_cnt[ee];
        s_off[tid] = o; g_off[tid] = o;
    }
    __syncthreads();

    int wb = 0;
    for (int w = 0; w < warp; w++) wb += s_wcnt[w][e];
    int slot = s_off[e] + wb + rin;
    g_tok[slot]  = t;
    g_wass[slot] = s_w[t][j];
}

// ---------------- zero the output (d_out is poisoned) ----------------
__global__ void zero_k(float4* __restrict__ out) {
    out[blockIdx.x * 256 + threadIdx.x] = make_float4(0.f, 0.f, 0.f, 0.f);
}

// ================= 2) gate/up GEMM: M=cnt, N=1408, K=2048 =================
// 256 threads (8 warps). Warp owns 4 output rows; 8 weight streams per stage
// (4 gate + 4 up), SINGLE pass over K (16 stages) so x is read from smem once.
// Stage = 4 KB/warp; ring 4 buffers, prefetch 3. x tile (<=12 tok) async.
#define GU_ROWS_BLK 32
#define GU_TILES    (INTER / GU_ROWS_BLK)   // 44
#define GU_X_U2     (12*512)                // 98304 B
#define GU_SMEM_B   (98304 + 8*4*4096)      // 229376

template<int TM>
__device__ __forceinline__ void gu_all(const float* __restrict__ wg_e,
                                       const float* __restrict__ wu_e,
                                       const ulonglong2* __restrict__ xs,
                                       const ulonglong2* __restrict__ wsh,
                                       uint32_t wbase,
                                       int row0, int slot0, int rem)
{
    const int warp = threadIdx.x >> 5, lane = threadIdx.x & 31;
    const int row = row0 + warp * 4;

    auto issue = [&](int g) {
        uint32_t dst = wbase + (g & 3) * 4096;
        #pragma unroll
        for (int r = 0; r < 4; r++) {
            cpa16(dst + r*512        + lane*16, wg_e + (size_t)(row+r)*HID + g*128 + lane*4);
            cpa16(dst + 2048 + r*512 + lane*16, wu_e + (size_t)(row+r)*HID + g*128 + lane*4);
        }
    };

    #pragma unroll
    for (int g = 0; g < 3; g++) { issue(g); cpa_commit(); }
    cpa_wait2();        // own x copies + stage0 complete
    __syncthreads();    // all threads' x copies visible

    ull ag[4][TM], au[4][TM];
    #pragma unroll
    for (int r = 0; r < 4; r++)
        #pragma unroll
        for (int t = 0; t < TM; t++) { ag[r][t] = 0ull; au[r][t] = 0ull; }

    #pragma unroll 1
    for (int s = 0; s < 16; s++) {
        cpa_wait2();
        int gn = s + 3;
        if (gn < 16) issue(gn);
        cpa_commit();

        const ulonglong2* wb = wsh + (s & 3) * 256;
        ulonglong2 w0 = wb[lane],     w1 = wb[32+lane],  w2 = wb[64+lane],  w3 = wb[96+lane];
        ulonglong2 u0 = wb[128+lane], u1 = wb[160+lane], u2 = wb[192+lane], u3 = wb[224+lane];
        int xo = s * 32 + lane;
        #pragma unroll
        for (int t = 0; t < TM; t++) {
            ulonglong2 xv = xs[t * 512 + xo];
            fma2(ag[0][t], w0.x, xv.x); fma2(ag[0][t], w0.y, xv.y);
            fma2(ag[1][t], w1.x, xv.x); fma2(ag[1][t], w1.y, xv.y);
            fma2(ag[2][t], w2.x, xv.x); fma2(ag[2][t], w2.y, xv.y);
            fma2(ag[3][t], w3.x, xv.x); fma2(ag[3][t], w3.y, xv.y);
            fma2(au[0][t], u0.x, xv.x); fma2(au[0][t], u0.y, xv.y);
            fma2(au[1][t], u1.x, xv.x); fma2(au[1][t], u1.y, xv.y);
            fma2(au[2][t], u2.x, xv.x); fma2(au[2][t], u2.y, xv.y);
            fma2(au[3][t], u3.x, xv.x); fma2(au[3][t], u3.y, xv.y);
        }
    }

    #pragma unroll
    for (int t = 0; t < TM; t++) {
        float gv[4], uv[4];
        #pragma unroll
        for (int r = 0; r < 4; r++) { gv[r] = hsum(ag[r][t]); uv[r] = hsum(au[r][t]); }
        if (lane == t && t < rem) {
            float* mp = g_mixed + (size_t)(slot0 + t) * INTER;
            #pragma unroll
            for (int r = 0; r < 4; r++) {
                float sv = gv[r] * __frcp_rn(1.f + __expf(-gv[r]));
                mp[row + r] = sv * uv[r];
            }
        }
    }
}

__global__ void __launch_bounds__(256, 1) gateup_k(const float* __restrict__ x,
                                                   const float* __restrict__ wg,
                                                   const float* __restrict__ wu)
{
    extern __shared__ ulonglong2 sh[];
    int e = blockIdx.y;
    int cnt = g_cnt[e];
    if (cnt == 0) return;
    int base = g_off[e];
    int row0 = blockIdx.x * GU_ROWS_BLK;
    const float* wg_e = wg + (size_t)e * INTER * HID;
    const float* wu_e = wu + (size_t)e * INTER * HID;

    uint32_t smem_u32 = (uint32_t)__cvta_generic_to_shared(sh);
    int warp = threadIdx.x >> 5;
    uint32_t wbase = smem_u32 + 98304 + warp * 16384;
    const ulonglong2* wsh = sh + GU_X_U2 + warp * 1024;

    for (int c0 = 0; c0 < cnt; c0 += 12) {
        int rem = cnt - c0; if (rem > 12) rem = 12;
        int tmv = rem + (rem & 1);                 // granularity 2
        __syncthreads();                           // prev consumers done with x
        for (int idx = rem * 512 + threadIdx.x; idx < tmv * 512; idx += 256) {
            ulonglong2 z; z.x = 0ull; z.y = 0ull; sh[idx] = z;
        }
        for (int idx = threadIdx.x; idx < rem * 512; idx += 256) {
            int slot = idx >> 9, j = idx & 511;
            int tok = g_tok[base + c0 + slot];
            cpa16(smem_u32 + idx * 16, x + (size_t)tok * HID + j * 4);
        }
        cpa_commit();
        switch (tmv) {
            case 2:  gu_all<2 >(wg_e, wu_e, sh, wsh, wbase, row0, base + c0, rem); break;
            case 4:  gu_all<4 >(wg_e, wu_e, sh, wsh, wbase, row0, base + c0, rem); break;
            case 6:  gu_all<6 >(wg_e, wu_e, sh, wsh, wbase, row0, base + c0, rem); break;
            case 8:  gu_all<8 >(wg_e, wu_e, sh, wsh, wbase, row0, base + c0, rem); break;
            case 10: gu_all<10>(wg_e, wu_e, sh, wsh, wbase, row0, base + c0, rem); break;
            default: gu_all<12>(wg_e, wu_e, sh, wsh, wbase, row0, base + c0, rem); break;
        }
    }
}

// ================= 3) down GEMM: M=cnt, N=2048, K=1408 ====================
// 256 threads (8 warps). Warp owns 8 rows = 8 streams, SINGLE pass (11
// stages). Stage 4 KB/warp; ring 4 buffers, prefetch 3. Fused atomicAdd out.
#define DN_ROWS_BLK 64
#define DN_TILES    (HID / DN_ROWS_BLK)     // 32
#define DN_X_U2     (12*352)                // 67584 B
#define DN_SMEM_B   (67584 + 8*4*4096)      // 198656

template<int TM>
__device__ __forceinline__ void dn_all(const float* __restrict__ wd_e,
                                       const ulonglong2* __restrict__ xs,
                                       const ulonglong2* __restrict__ wsh,
                                       uint32_t wbase,
                                       int row0, int slot0, int rem,
                                       float* __restrict__ out)
{
    const int warp = threadIdx.x >> 5, lane = threadIdx.x & 31;
    const int row = row0 + warp * 8;

    auto issue = [&](int g) {
        uint32_t dst = wbase + (g & 3) * 4096;
        #pragma unroll
        for (int r = 0; r < 8; r++)
            cpa16(dst + r*512 + lane*16, wd_e + (size_t)(row+r)*INTER + g*128 + lane*4);
    };

    #pragma unroll
    for (int g = 0; g < 3; g++) { issue(g); cpa_commit(); }
    cpa_wait2();
    __syncthreads();

    ull acc[8][TM];
    #pragma unroll
    for (int r = 0; r < 8; r++)
        #pragma unroll
        for (int t = 0; t < TM; t++) acc[r][t] = 0ull;

    #pragma unroll 1
    for (int s = 0; s < 11; s++) {
        cpa_wait2();
        int gn = s + 3;
        if (gn < 11) issue(gn);
        cpa_commit();

        const ulonglong2* wb = wsh + (s & 3) * 256;
        ulonglong2 w0 = wb[lane],     w1 = wb[32+lane],  w2 = wb[64+lane],  w3 = wb[96+lane];
        ulonglong2 w4 = wb[128+lane], w5 = wb[160+lane], w6 = wb[192+lane], w7 = wb[224+lane];
        int xo = s * 32 + lane;
        #pragma unroll
        for (int t = 0; t < TM; t++) {
            ulonglong2 xv = xs[t * 352 + xo];
            fma2(acc[0][t], w0.x, xv.x); fma2(acc[0][t], w0.y, xv.y);
            fma2(acc[1][t], w1.x, xv.x); fma2(acc[1][t], w1.y, xv.y);
            fma2(acc[2][t], w2.x, xv.x); fma2(acc[2][t], w2.y, xv.y);
            fma2(acc[3][t], w3.x, xv.x); fma2(acc[3][t], w3.y, xv.y);
            fma2(acc[4][t], w4.x, xv.x); fma2(acc[4][t], w4.y, xv.y);
            fma2(acc[5][t], w5.x, xv.x); fma2(acc[5][t], w5.y, xv.y);
            fma2(acc[6][t], w6.x, xv.x); fma2(acc[6][t], w6.y, xv.y);
            fma2(acc[7][t], w7.x, xv.x); fma2(acc[7][t], w7.y, xv.y);
        }
    }

    #pragma unroll
    for (int t = 0; t < TM; t++) {
        float v[8];
        #pragma unroll
        for (int r = 0; r < 8; r++) v[r] = hsum(acc[r][t]);
        if (lane == t && t < rem) {
            float w = g_wass[slot0 + t];
            int tok = g_tok[slot0 + t];
            float* op = out + (size_t)tok * HID + row;
            #pragma unroll
            for (int r = 0; r < 8; r++) atomicAdd(op + r, v[r] * w);
        }
    }
}

__global__ void __launch_bounds__(256, 1) down_k(const float* __restrict__ wd,
                                                 float* __restrict__ out)
{
    extern __shared__ ulonglong2 sh[];
    int e = blockIdx.y;
    int cnt = g_cnt[e];
    if (cnt == 0) return;
    int base = g_off[e];
    int row0 = blockIdx.x * DN_ROWS_BLK;
    const float* wd_e = wd + (size_t)e * HID * INTER;

    uint32_t smem_u32 = (uint32_t)__cvta_generic_to_shared(sh);
    int warp = threadIdx.x >> 5;
    uint32_t wbase = smem_u32 + 67584 + warp * 16384;
    const ulonglong2* wsh = sh + DN_X_U2 + warp * 1024;

    for (int c0 = 0; c0 < cnt; c0 += 12) {
        int rem = cnt - c0; if (rem > 12) rem = 12;
        int tmv = rem + (rem & 1);
        __syncthreads();
        for (int idx = rem * 352 + threadIdx.x; idx < tmv * 352; idx += 256) {
            ulonglong2 z; z.x = 0ull; z.y = 0ull; sh[idx] = z;
        }
        for (int idx = threadIdx.x; idx < rem * 352; idx += 256) {
            int slot = idx / 352, j = idx - slot * 352;
            cpa16(smem_u32 + idx * 16,
                  g_mixed + (size_t)(base + c0 + slot) * INTER + j * 4);
        }
        cpa_commit();
        switch (tmv) {
            case 2:  dn_all<2 >(wd_e, sh, wsh, wbase, row0, base + c0, rem, out); break;
            case 4:  dn_all<4 >(wd_e, sh, wsh, wbase, row0, base + c0, rem, out); break;
            case 6:  dn_all<6 >(wd_e, sh, wsh, wbase, row0, base + c0, rem, out); break;
            case 8:  dn_all<8 >(wd_e, sh, wsh, wbase, row0, base + c0, rem, out); break;
            case 10: dn_all<10>(wd_e, sh, wsh, wbase, row0, base + c0, rem, out); break;
            default: dn_all<12>(wd_e, sh, wsh, wbase, row0, base + c0, rem, out); break;
        }
    }
}

// ---------------- launch ----------------
extern "C" void kernel_launch(void* const* d_in, const int* in_sizes, int n_in,
                              void* d_out, int out_size)
{
    const float* x      = (const float*)d_in[0];
    const float* logits = (const float*)d_in[1];
    const float* wg     = (const float*)d_in[2];
    const float* wu     = (const float*)d_in[3];
    const float* wd     = (const float*)d_in[4];
    float* out = (float*)d_out;

    cudaFuncSetAttribute(gateup_k, cudaFuncAttributeMaxDynamicSharedMemorySize, GU_SMEM_B);
    cudaFuncSetAttribute(down_k,   cudaFuncAttributeMaxDynamicSharedMemorySize, DN_SMEM_B);

    route_k<<<1, 256>>>(logits);
    zero_k<<<(NTOK * HID) / 1024, 256>>>((float4*)out);
    gateup_k<<<dim3(GU_TILES, NEXP), 256, GU_SMEM_B>>>(x, wg, wu);
    down_k  <<<dim3(DN_TILES, NEXP), 256, DN_SMEM_B>>>(wd, out);
}

// round 15
// speedup vs baseline: 1.0542x; 1.0542x over previous
#include <cuda_runtime.h>
#include <cstdint>

#define NTOK  64
#define HID   2048
#define INTER 1408
#define NEXP  32
#define TOPK  4
#define NASS  (NTOK*TOPK)

typedef unsigned long long ull;

// ---------------- scratch ----------------
__device__ int   g_cnt[NEXP];
__device__ int   g_off[NEXP];
__device__ int   g_tok[NASS];
__device__ float g_wass[NASS];
__device__ float g_mixed[(size_t)NASS*INTER];

// ---------------- f32x2 packed FMA ----------------
__device__ __forceinline__ void fma2(ull &a, ull b, ull c) {
    asm("fma.rn.f32x2 %0, %1, %2, %0;" : "+l"(a) : "l"(b), "l"(c));
}
__device__ __forceinline__ float hsum(ull a) {
    float lo = __uint_as_float((unsigned)a);
    float hi = __uint_as_float((unsigned)(a >> 32));
    float s = lo + hi;
    #pragma unroll
    for (int o = 16; o > 0; o >>= 1) s += __shfl_xor_sync(0xffffffffu, s, o);
    return s;
}

// ---------------- cp.async helpers ----------------
__device__ __forceinline__ void cpa16(uint32_t dst, const float* src) {
    asm volatile("cp.async.cg.shared.global [%0], [%1], 16;" :: "r"(dst), "l"(src));
}
__device__ __forceinline__ void cpa_commit() { asm volatile("cp.async.commit_group;"); }
__device__ __forceinline__ void cpa_wait2()  { asm volatile("cp.async.wait_group 2;"); }
__device__ __forceinline__ void cpa_wait3()  { asm volatile("cp.async.wait_group 3;"); }

// ---------------- 1) routing: ballot-ranked, 256 threads ----------------
__global__ void route_k(const float* __restrict__ logits) {
    __shared__ int   s_ids[NTOK][TOPK];
    __shared__ float s_w  [NTOK][TOPK];
    __shared__ int   s_wcnt[8][NEXP];
    __shared__ int   s_cnt[NEXP];
    __shared__ int   s_off[NEXP];
    int tid = threadIdx.x;

    ((int*)s_wcnt)[tid] = 0;

    if (tid < NTOK) {
        int t = tid;
        float v[NEXP];
        #pragma unroll
        for (int e = 0; e < NEXP; e++) v[e] = logits[t*NEXP + e];

        int ids[TOPK]; float vals[TOPK];
        #pragma unroll
        for (int j = 0; j < TOPK; j++) {
            int bi = 0; float bv = -1e30f;
            #pragma unroll
            for (int e = 0; e < NEXP; e++) if (v[e] > bv) { bv = v[e]; bi = e; }
            ids[j] = bi; vals[j] = bv; v[bi] = -1e30f;
        }
        float m = vals[0], s = 0.f, w[TOPK];
        #pragma unroll
        for (int j = 0; j < TOPK; j++) { w[j] = __expf(vals[j] - m); s += w[j]; }
        float inv = 1.f / s;
        #pragma unroll
        for (int j = 0; j < TOPK; j++) { s_ids[t][j] = ids[j]; s_w[t][j] = w[j] * inv; }
    }
    __syncthreads();

    int a = tid, t = a >> 2, j = a & 3;
    int e = s_ids[t][j];
    int warp = a >> 5, lane = a & 31;
    unsigned mask = __match_any_sync(0xffffffffu, e);
    int rin = __popc(mask & ((1u << lane) - 1u));
    if (rin == 0) s_wcnt[warp][e] = __popc(mask);
    __syncthreads();

    if (tid < NEXP) {
        int c = 0;
        #pragma unroll
        for (int w = 0; w < 8; w++) c += s_wcnt[w][tid];
        s_cnt[tid] = c; g_cnt[tid] = c;
    }
    __syncthreads();
    if (tid < NEXP) {
        int o = 0;
        for (int ee = 0; ee < tid; ee++) o += s_cnt[ee];
        s_off[tid] = o; g_off[tid] = o;
    }
    __syncthreads();

    int wb = 0;
    for (int w = 0; w < warp; w++) wb += s_wcnt[w][e];
    int slot = s_off[e] + wb + rin;
    g_tok[slot]  = t;
    g_wass[slot] = s_w[t][j];
}

// ---------------- zero the output (d_out is poisoned) ----------------
__global__ void zero_k(float4* __restrict__ out) {
    out[blockIdx.x * 256 + threadIdx.x] = make_float4(0.f, 0.f, 0.f, 0.f);
}

// ================= 2) gate/up GEMM: M=cnt, N=1408, K=2048 =================
// R13 config (measured best): 512 threads (16 warps). Warp owns 4 rows =
// 2 row-pair passes (4 streams each). Per-warp ring: 4 buffers x 2 KB,
// prefetch depth 3, continuous over 32 global stages. x tile <=12 tokens.
#define GU_ROWS_BLK 64
#define GU_TILES    (INTER / GU_ROWS_BLK)   // 22
#define GU_X_U2     (12*512)                // 98304 B
#define GU_SMEM_B   (98304 + 16*4*2048)     // 229376

template<int TM>
__device__ __forceinline__ void gu_all(const float* __restrict__ wg_e,
                                       const float* __restrict__ wu_e,
                                       const ulonglong2* __restrict__ xs,
                                       const ulonglong2* __restrict__ wsh,
                                       uint32_t wbase,
                                       int row0, int slot0, int rem)
{
    const int warp = threadIdx.x >> 5, lane = threadIdx.x & 31;

    auto issue = [&](int g) {
        int rp2 = g >> 4, s2 = g & 15;
        int row2 = row0 + warp * 4 + rp2 * 2;
        const float* f0 = wg_e + (size_t)row2     * HID + s2 * 128;
        const float* f1 = wg_e + (size_t)(row2+1) * HID + s2 * 128;
        const float* f2 = wu_e + (size_t)row2     * HID + s2 * 128;
        const float* f3 = wu_e + (size_t)(row2+1) * HID + s2 * 128;
        uint32_t dst = wbase + (g & 3) * 2048;
        cpa16(dst +         lane*16, f0 + lane*4);
        cpa16(dst +  512 +  lane*16, f1 + lane*4);
        cpa16(dst + 1024 +  lane*16, f2 + lane*4);
        cpa16(dst + 1536 +  lane*16, f3 + lane*4);
    };

    #pragma unroll
    for (int g = 0; g < 3; g++) { issue(g); cpa_commit(); }
    cpa_wait2();        // own x copies + W0 complete
    __syncthreads();    // all threads' x copies visible

    #pragma unroll 1
    for (int rp = 0; rp < 2; rp++) {
        int row = row0 + warp * 4 + rp * 2;
        ull ag0[TM], ag1[TM], au0[TM], au1[TM];
        #pragma unroll
        for (int t = 0; t < TM; t++) { ag0[t]=0ull; ag1[t]=0ull; au0[t]=0ull; au1[t]=0ull; }

        #pragma unroll 1
        for (int s = 0; s < 16; s++) {
            int gs = rp * 16 + s;
            cpa_wait2();
            int gn = gs + 3;
            if (gn < 32) issue(gn);
            cpa_commit();

            const ulonglong2* wb = wsh + (gs & 3) * 128;
            ulonglong2 a0 = wb[lane], a1 = wb[32+lane], b0 = wb[64+lane], b1 = wb[96+lane];
            int xo = s * 32 + lane;
            #pragma unroll
            for (int t = 0; t < TM; t++) {
                ulonglong2 xv = xs[t * 512 + xo];
                fma2(ag0[t], a0.x, xv.x); fma2(ag0[t], a0.y, xv.y);
                fma2(ag1[t], a1.x, xv.x); fma2(ag1[t], a1.y, xv.y);
                fma2(au0[t], b0.x, xv.x); fma2(au0[t], b0.y, xv.y);
                fma2(au1[t], b1.x, xv.x); fma2(au1[t], b1.y, xv.y);
            }
        }

        #pragma unroll
        for (int t = 0; t < TM; t++) {
            float gA = hsum(ag0[t]);
            float gB = hsum(ag1[t]);
            float uA = hsum(au0[t]);
            float uB = hsum(au1[t]);
            if (lane == t && t < rem) {
                float sA = gA * __frcp_rn(1.f + __expf(-gA));
                float sB = gB * __frcp_rn(1.f + __expf(-gB));
                float* mp = g_mixed + (size_t)(slot0 + t) * INTER;
                mp[row]     = sA * uA;
                mp[row + 1] = sB * uB;
            }
        }
    }
}

__global__ void __launch_bounds__(512, 1) gateup_k(const float* __restrict__ x,
                                                   const float* __restrict__ wg,
                                                   const float* __restrict__ wu)
{
    extern __shared__ ulonglong2 sh[];
    int e = blockIdx.y;
    int cnt = g_cnt[e];
    if (cnt == 0) return;
    int base = g_off[e];
    int row0 = blockIdx.x * GU_ROWS_BLK;
    const float* wg_e = wg + (size_t)e * INTER * HID;
    const float* wu_e = wu + (size_t)e * INTER * HID;

    uint32_t smem_u32 = (uint32_t)__cvta_generic_to_shared(sh);
    int warp = threadIdx.x >> 5;
    uint32_t wbase = smem_u32 + 98304 + warp * 8192;
    const ulonglong2* wsh = sh + GU_X_U2 + warp * 512;

    for (int c0 = 0; c0 < cnt; c0 += 12) {
        int rem = cnt - c0; if (rem > 12) rem = 12;
        int tmv = rem + (rem & 1);                 // granularity 2
        __syncthreads();                           // prev consumers done with x
        for (int idx = rem * 512 + threadIdx.x; idx < tmv * 512; idx += 512) {
            ulonglong2 z; z.x = 0ull; z.y = 0ull; sh[idx] = z;
        }
        for (int idx = threadIdx.x; idx < rem * 512; idx += 512) {
            int slot = idx >> 9, j = idx & 511;
            int tok = g_tok[base + c0 + slot];
            cpa16(smem_u32 + idx * 16, x + (size_t)tok * HID + j * 4);
        }
        cpa_commit();
        switch (tmv) {
            case 2:  gu_all<2 >(wg_e, wu_e, sh, wsh, wbase, row0, base + c0, rem); break;
            case 4:  gu_all<4 >(wg_e, wu_e, sh, wsh, wbase, row0, base + c0, rem); break;
            case 6:  gu_all<6 >(wg_e, wu_e, sh, wsh, wbase, row0, base + c0, rem); break;
            case 8:  gu_all<8 >(wg_e, wu_e, sh, wsh, wbase, row0, base + c0, rem); break;
            case 10: gu_all<10>(wg_e, wu_e, sh, wsh, wbase, row0, base + c0, rem); break;
            default: gu_all<12>(wg_e, wu_e, sh, wsh, wbase, row0, base + c0, rem); break;
        }
    }
}

// ================= 3) down GEMM: M=cnt, N=2048, K=1408 ====================
// 512 threads (16 warps), warp owns 4 rows = 1 quad, 11 stages. Ring
// DEEPENED to 5 buffers x 2 KB, prefetch depth 4 (wait_group 3) ->
// in-flight 8 KB/warp, 128 KB/SM. Fused weighted atomicAdd output.
#define DN_ROWS_BLK 64
#define DN_TILES    (HID / DN_ROWS_BLK)     // 32
#define DN_X_U2     (12*352)                // 67584 B
#define DN_SMEM_B   (67584 + 16*5*2048)     // 231424

template<int TM>
__device__ __forceinline__ void dn_all(const float* __restrict__ wd_e,
                                       const ulonglong2* __restrict__ xs,
                                       const ulonglong2* __restrict__ wsh,
                                       uint32_t wbase,
                                       int row0, int slot0, int rem,
                                       float* __restrict__ out)
{
    const int warp = threadIdx.x >> 5, lane = threadIdx.x & 31;
    int row = row0 + warp * 4;

    // slot argument is the explicit ring slot (0..4); avoids mod-5 chains.
    auto issue = [&](int g, int slot) {
        const float* f0 = wd_e + (size_t)(row  ) * INTER + g * 128;
        const float* f1 = wd_e + (size_t)(row+1) * INTER + g * 128;
        const float* f2 = wd_e + (size_t)(row+2) * INTER + g * 128;
        const float* f3 = wd_e + (size_t)(row+3) * INTER + g * 128;
        uint32_t dst = wbase + slot * 2048;
        cpa16(dst +         lane*16, f0 + lane*4);
        cpa16(dst +  512 +  lane*16, f1 + lane*4);
        cpa16(dst + 1024 +  lane*16, f2 + lane*4);
        cpa16(dst + 1536 +  lane*16, f3 + lane*4);
    };

    #pragma unroll
    for (int g = 0; g < 4; g++) { issue(g, g); cpa_commit(); }
    cpa_wait3();        // own x copies + stage0 complete
    __syncthreads();

    ull a0[TM], a1[TM], a2[TM], a3[TM];
    #pragma unroll
    for (int t = 0; t < TM; t++) { a0[t]=0ull; a1[t]=0ull; a2[t]=0ull; a3[t]=0ull; }

    int rslot = 0, wslot = 4;   // reader slot for stage s; writer slot for s+4
    #pragma unroll 1
    for (int s = 0; s < 11; s++) {
        cpa_wait3();
        int gn = s + 4;
        if (gn < 11) issue(gn, wslot);
        cpa_commit();

        const ulonglong2* wb = wsh + rslot * 128;
        ulonglong2 w0 = wb[lane], w1 = wb[32+lane], w2 = wb[64+lane], w3 = wb[96+lane];
        int xo = s * 32 + lane;
        #pragma unroll
        for (int t = 0; t < TM; t++) {
            ulonglong2 xv = xs[t * 352 + xo];
            fma2(a0[t], w0.x, xv.x); fma2(a0[t], w0.y, xv.y);
            fma2(a1[t], w1.x, xv.x); fma2(a1[t], w1.y, xv.y);
            fma2(a2[t], w2.x, xv.x); fma2(a2[t], w2.y, xv.y);
            fma2(a3[t], w3.x, xv.x); fma2(a3[t], w3.y, xv.y);
        }
        rslot = (rslot == 4) ? 0 : rslot + 1;
        wslot = (wslot == 4) ? 0 : wslot + 1;
    }

    #pragma unroll
    for (int t = 0; t < TM; t++) {
        float v0 = hsum(a0[t]);
        float v1 = hsum(a1[t]);
        float v2 = hsum(a2[t]);
        float v3 = hsum(a3[t]);
        if (lane == t && t < rem) {
            float w = g_wass[slot0 + t];
            int tok = g_tok[slot0 + t];
            float* op = out + (size_t)tok * HID + row;
            atomicAdd(op + 0, v0 * w);
            atomicAdd(op + 1, v1 * w);
            atomicAdd(op + 2, v2 * w);
            atomicAdd(op + 3, v3 * w);
        }
    }
}

__global__ void __launch_bounds__(512, 1) down_k(const float* __restrict__ wd,
                                                 float* __restrict__ out)
{
    extern __shared__ ulonglong2 sh[];
    int e = blockIdx.y;
    int cnt = g_cnt[e];
    if (cnt == 0) return;
    int base = g_off[e];
    int row0 = blockIdx.x * DN_ROWS_BLK;
    const float* wd_e = wd + (size_t)e * HID * INTER;

    uint32_t smem_u32 = (uint32_t)__cvta_generic_to_shared(sh);
    int warp = threadIdx.x >> 5;
    uint32_t wbase = smem_u32 + 67584 + warp * 10240;
    const ulonglong2* wsh = sh + DN_X_U2 + warp * 640;

    for (int c0 = 0; c0 < cnt; c0 += 12) {
        int rem = cnt - c0; if (rem > 12) rem = 12;
        int tmv = rem + (rem & 1);
        __syncthreads();
        for (int idx = rem * 352 + threadIdx.x; idx < tmv * 352; idx += 512) {
            ulonglong2 z; z.x = 0ull; z.y = 0ull; sh[idx] = z;
        }
        for (int idx = threadIdx.x; idx < rem * 352; idx += 512) {
            int slot = idx / 352, j = idx - slot * 352;
            cpa16(smem_u32 + idx * 16,
                  g_mixed + (size_t)(base + c0 + slot) * INTER + j * 4);
        }
        cpa_commit();
        switch (tmv) {
            case 2:  dn_all<2 >(wd_e, sh, wsh, wbase, row0, base + c0, rem, out); break;
            case 4:  dn_all<4 >(wd_e, sh, wsh, wbase, row0, base + c0, rem, out); break;
            case 6:  dn_all<6 >(wd_e, sh, wsh, wbase, row0, base + c0, rem, out); break;
            case 8:  dn_all<8 >(wd_e, sh, wsh, wbase, row0, base + c0, rem, out); break;
            case 10: dn_all<10>(wd_e, sh, wsh, wbase, row0, base + c0, rem, out); break;
            default: dn_all<12>(wd_e, sh, wsh, wbase, row0, base + c0, rem, out); break;
        }
    }
}

// ---------------- launch ----------------
extern "C" void kernel_launch(void* const* d_in, const int* in_sizes, int n_in,
                              void* d_out, int out_size)
{
    const float* x      = (const float*)d_in[0];
    const float* logits = (const float*)d_in[1];
    const float* wg     = (const float*)d_in[2];
    const float* wu     = (const float*)d_in[3];
    const float* wd     = (const float*)d_in[4];
    float* out = (float*)d_out;

    cudaFuncSetAttribute(gateup_k, cudaFuncAttributeMaxDynamicSharedMemorySize, GU_SMEM_B);
    cudaFuncSetAttribute(down_k,   cudaFuncAttributeMaxDynamicSharedMemorySize, DN_SMEM_B);

    route_k<<<1, 256>>>(logits);
    zero_k<<<(NTOK * HID) / 1024, 256>>>((float4*)out);
    gateup_k<<<dim3(GU_TILES, NEXP), 512, GU_SMEM_B>>>(x, wg, wu);
    down_k  <<<dim3(DN_TILES, NEXP), 512, DN_SMEM_B>>>(wd, out);
}

// round 16
// speedup vs baseline: 1.0832x; 1.0275x over previous
#include <cuda_runtime.h>
#include <cstdint>

#define NTOK  64
#define HID   2048
#define INTER 1408
#define NEXP  32
#define TOPK  4
#define NASS  (NTOK*TOPK)

typedef unsigned long long ull;

// ---------------- scratch ----------------
__device__ int   g_cnt[NEXP];
__device__ int   g_off[NEXP];
__device__ int   g_tok[NASS];
__device__ float g_wass[NASS];
__device__ float g_mixed[(size_t)NASS*INTER];

// ---------------- f32x2 packed FMA ----------------
__device__ __forceinline__ void fma2(ull &a, ull b, ull c) {
    asm("fma.rn.f32x2 %0, %1, %2, %0;" : "+l"(a) : "l"(b), "l"(c));
}
__device__ __forceinline__ float hsum(ull a) {
    float lo = __uint_as_float((unsigned)a);
    float hi = __uint_as_float((unsigned)(a >> 32));
    float s = lo + hi;
    #pragma unroll
    for (int o = 16; o > 0; o >>= 1) s += __shfl_xor_sync(0xffffffffu, s, o);
    return s;
}

// ---------------- cp.async helpers ----------------
__device__ __forceinline__ void cpa16(uint32_t dst, const float* src) {
    asm volatile("cp.async.cg.shared.global [%0], [%1], 16;" :: "r"(dst), "l"(src));
}
__device__ __forceinline__ void cpa_commit() { asm volatile("cp.async.commit_group;"); }
__device__ __forceinline__ void cpa_wait0()  { asm volatile("cp.async.wait_group 0;"); }
__device__ __forceinline__ void cpa_wait2()  { asm volatile("cp.async.wait_group 2;"); }

// ---------------- 1) routing: ballot-ranked, 256 threads ----------------
__global__ void route_k(const float* __restrict__ logits) {
    __shared__ int   s_ids[NTOK][TOPK];
    __shared__ float s_w  [NTOK][TOPK];
    __shared__ int   s_wcnt[8][NEXP];
    __shared__ int   s_cnt[NEXP];
    __shared__ int   s_off[NEXP];
    int tid = threadIdx.x;

    ((int*)s_wcnt)[tid] = 0;

    if (tid < NTOK) {
        int t = tid;
        float v[NEXP];
        #pragma unroll
        for (int e = 0; e < NEXP; e++) v[e] = logits[t*NEXP + e];

        int ids[TOPK]; float vals[TOPK];
        #pragma unroll
        for (int j = 0; j < TOPK; j++) {
            int bi = 0; float bv = -1e30f;
            #pragma unroll
            for (int e = 0; e < NEXP; e++) if (v[e] > bv) { bv = v[e]; bi = e; }
            ids[j] = bi; vals[j] = bv; v[bi] = -1e30f;
        }
        float m = vals[0], s = 0.f, w[TOPK];
        #pragma unroll
        for (int j = 0; j < TOPK; j++) { w[j] = __expf(vals[j] - m); s += w[j]; }
        float inv = 1.f / s;
        #pragma unroll
        for (int j = 0; j < TOPK; j++) { s_ids[t][j] = ids[j]; s_w[t][j] = w[j] * inv; }
    }
    __syncthreads();

    int a = tid, t = a >> 2, j = a & 3;
    int e = s_ids[t][j];
    int warp = a >> 5, lane = a & 31;
    unsigned mask = __match_any_sync(0xffffffffu, e);
    int rin = __popc(mask & ((1u << lane) - 1u));
    if (rin == 0) s_wcnt[warp][e] = __popc(mask);
    __syncthreads();

    if (tid < NEXP) {
        int c = 0;
        #pragma unroll
        for (int w = 0; w < 8; w++) c += s_wcnt[w][tid];
        s_cnt[tid] = c; g_cnt[tid] = c;
    }
    __syncthreads();
    if (tid < NEXP) {
        int o = 0;
        for (int ee = 0; ee < tid; ee++) o += s_cnt[ee];
        s_off[tid] = o; g_off[tid] = o;
    }
    __syncthreads();

    int wb = 0;
    for (int w = 0; w < warp; w++) wb += s_wcnt[w][e];
    int slot = s_off[e] + wb + rin;
    g_tok[slot]  = t;
    g_wass[slot] = s_w[t][j];
}

// ---------------- zero the output (d_out is poisoned) ----------------
__global__ void zero_k(float4* __restrict__ out) {
    out[blockIdx.x * 256 + threadIdx.x] = make_float4(0.f, 0.f, 0.f, 0.f);
}

// ================= 2) gate/up GEMM: M=cnt, N=1408, K=2048 =================
// R13 config (measured best): 512 threads (16 warps). Warp owns 4 rows =
// 2 row-pair passes (4 streams each). Per-warp ring: 4 buffers x 2 KB,
// prefetch depth 3, continuous over 32 global stages. x tile <=12 tokens.
#define GU_ROWS_BLK 64
#define GU_TILES    (INTER / GU_ROWS_BLK)   // 22
#define GU_X_U2     (12*512)                // 98304 B
#define GU_SMEM_B   (98304 + 16*4*2048)     // 229376

template<int TM>
__device__ __forceinline__ void gu_all(const float* __restrict__ wg_e,
                                       const float* __restrict__ wu_e,
                                       const ulonglong2* __restrict__ xs,
                                       const ulonglong2* __restrict__ wsh,
                                       uint32_t wbase,
                                       int row0, int slot0, int rem)
{
    const int warp = threadIdx.x >> 5, lane = threadIdx.x & 31;

    auto issue = [&](int g) {
        int rp2 = g >> 4, s2 = g & 15;
        int row2 = row0 + warp * 4 + rp2 * 2;
        const float* f0 = wg_e + (size_t)row2     * HID + s2 * 128;
        const float* f1 = wg_e + (size_t)(row2+1) * HID + s2 * 128;
        const float* f2 = wu_e + (size_t)row2     * HID + s2 * 128;
        const float* f3 = wu_e + (size_t)(row2+1) * HID + s2 * 128;
        uint32_t dst = wbase + (g & 3) * 2048;
        cpa16(dst +         lane*16, f0 + lane*4);
        cpa16(dst +  512 +  lane*16, f1 + lane*4);
        cpa16(dst + 1024 +  lane*16, f2 + lane*4);
        cpa16(dst + 1536 +  lane*16, f3 + lane*4);
    };

    #pragma unroll
    for (int g = 0; g < 3; g++) { issue(g); cpa_commit(); }
    cpa_wait2();        // own x copies + W0 complete
    __syncthreads();    // all threads' x copies visible

    #pragma unroll 1
    for (int rp = 0; rp < 2; rp++) {
        int row = row0 + warp * 4 + rp * 2;
        ull ag0[TM], ag1[TM], au0[TM], au1[TM];
        #pragma unroll
        for (int t = 0; t < TM; t++) { ag0[t]=0ull; ag1[t]=0ull; au0[t]=0ull; au1[t]=0ull; }

        #pragma unroll 1
        for (int s = 0; s < 16; s++) {
            int gs = rp * 16 + s;
            cpa_wait2();
            int gn = gs + 3;
            if (gn < 32) issue(gn);
            cpa_commit();

            const ulonglong2* wb = wsh + (gs & 3) * 128;
            ulonglong2 a0 = wb[lane], a1 = wb[32+lane], b0 = wb[64+lane], b1 = wb[96+lane];
            int xo = s * 32 + lane;
            #pragma unroll
            for (int t = 0; t < TM; t++) {
                ulonglong2 xv = xs[t * 512 + xo];
                fma2(ag0[t], a0.x, xv.x); fma2(ag0[t], a0.y, xv.y);
                fma2(ag1[t], a1.x, xv.x); fma2(ag1[t], a1.y, xv.y);
                fma2(au0[t], b0.x, xv.x); fma2(au0[t], b0.y, xv.y);
                fma2(au1[t], b1.x, xv.x); fma2(au1[t], b1.y, xv.y);
            }
        }

        #pragma unroll
        for (int t = 0; t < TM; t++) {
            float gA = hsum(ag0[t]);
            float gB = hsum(ag1[t]);
            float uA = hsum(au0[t]);
            float uB = hsum(au1[t]);
            if (lane == t && t < rem) {
                float sA = gA * __frcp_rn(1.f + __expf(-gA));
                float sB = gB * __frcp_rn(1.f + __expf(-gB));
                float* mp = g_mixed + (size_t)(slot0 + t) * INTER;
                mp[row]     = sA * uA;
                mp[row + 1] = sB * uB;
            }
        }
    }
}

__global__ void __launch_bounds__(512, 1) gateup_k(const float* __restrict__ x,
                                                   const float* __restrict__ wg,
                                                   const float* __restrict__ wu)
{
    extern __shared__ ulonglong2 sh[];
    int e = blockIdx.y;
    int cnt = g_cnt[e];
    if (cnt == 0) return;
    int base = g_off[e];
    int row0 = blockIdx.x * GU_ROWS_BLK;
    const float* wg_e = wg + (size_t)e * INTER * HID;
    const float* wu_e = wu + (size_t)e * INTER * HID;

    uint32_t smem_u32 = (uint32_t)__cvta_generic_to_shared(sh);
    int warp = threadIdx.x >> 5;
    uint32_t wbase = smem_u32 + 98304 + warp * 8192;
    const ulonglong2* wsh = sh + GU_X_U2 + warp * 512;

    for (int c0 = 0; c0 < cnt; c0 += 12) {
        int rem = cnt - c0; if (rem > 12) rem = 12;
        int tmv = rem + (rem & 1);                 // granularity 2
        __syncthreads();                           // prev consumers done with x
        for (int idx = rem * 512 + threadIdx.x; idx < tmv * 512; idx += 512) {
            ulonglong2 z; z.x = 0ull; z.y = 0ull; sh[idx] = z;
        }
        for (int idx = threadIdx.x; idx < rem * 512; idx += 512) {
            int slot = idx >> 9, j = idx & 511;
            int tok = g_tok[base + c0 + slot];
            cpa16(smem_u32 + idx * 16, x + (size_t)tok * HID + j * 4);
        }
        cpa_commit();
        switch (tmv) {
            case 2:  gu_all<2 >(wg_e, wu_e, sh, wsh, wbase, row0, base + c0, rem); break;
            case 4:  gu_all<4 >(wg_e, wu_e, sh, wsh, wbase, row0, base + c0, rem); break;
            case 6:  gu_all<6 >(wg_e, wu_e, sh, wsh, wbase, row0, base + c0, rem); break;
            case 8:  gu_all<8 >(wg_e, wu_e, sh, wsh, wbase, row0, base + c0, rem); break;
            case 10: gu_all<10>(wg_e, wu_e, sh, wsh, wbase, row0, base + c0, rem); break;
            default: gu_all<12>(wg_e, wu_e, sh, wsh, wbase, row0, base + c0, rem); break;
        }
    }
}

// ================= 3) down GEMM: M=cnt, N=2048, K=1408 ====================
// R13 loop (measured 87.5us), restructured for PDL: the chunk weight prologue
// is issued by the caller BEFORE cudaGridDependencySynchronize(), so down
// blocks prefetch weights while gateup's tail drains. dn_all assumes groups
// [W0,W1,W2,X] are in flight, drains them, then runs the R13 mainloop
// (wait2, issue W(s+3) into slot (s+3)&3, read slot s&3, empty-commit tail).
#define DN_ROWS_BLK 64
#define DN_TILES    (HID / DN_ROWS_BLK)     // 32
#define DN_X_U2     (12*352)                // 67584 B
#define DN_SMEM_B   (67584 + 16*4*2048)     // 198656

template<int TM>
__device__ __forceinline__ void dn_all(const float* __restrict__ wd_e,
                                       const ulonglong2* __restrict__ xs,
                                       const ulonglong2* __restrict__ wsh,
                                       uint32_t wbase,
                                       int row0, int slot0, int rem,
                                       float* __restrict__ out)
{
    const int warp = threadIdx.x >> 5, lane = threadIdx.x & 31;
    int row = row0 + warp * 4;

    auto issue = [&](int g) {
        const float* f0 = wd_e + (size_t)(row  ) * INTER + g * 128;
        const float* f1 = wd_e + (size_t)(row+1) * INTER + g * 128;
        const float* f2 = wd_e + (size_t)(row+2) * INTER + g * 128;
        const float* f3 = wd_e + (size_t)(row+3) * INTER + g * 128;
        uint32_t dst = wbase + (g & 3) * 2048;
        cpa16(dst +         lane*16, f0 + lane*4);
        cpa16(dst +  512 +  lane*16, f1 + lane*4);
        cpa16(dst + 1024 +  lane*16, f2 + lane*4);
        cpa16(dst + 1536 +  lane*16, f3 + lane*4);
    };

    cpa_wait0();        // W0..W2 + X all resident
    __syncthreads();    // all threads' x copies visible

    ull a0[TM], a1[TM], a2[TM], a3[TM];
    #pragma unroll
    for (int t = 0; t < TM; t++) { a0[t]=0ull; a1[t]=0ull; a2[t]=0ull; a3[t]=0ull; }

    #pragma unroll 1
    for (int s = 0; s < 11; s++) {
        cpa_wait2();
        int gn = s + 3;
        if (gn < 11) issue(gn);
        cpa_commit();

        const ulonglong2* wb = wsh + (s & 3) * 128;
        ulonglong2 w0 = wb[lane], w1 = wb[32+lane], w2 = wb[64+lane], w3 = wb[96+lane];
        int xo = s * 32 + lane;
        #pragma unroll
        for (int t = 0; t < TM; t++) {
            ulonglong2 xv = xs[t * 352 + xo];
            fma2(a0[t], w0.x, xv.x); fma2(a0[t], w0.y, xv.y);
            fma2(a1[t], w1.x, xv.x); fma2(a1[t], w1.y, xv.y);
            fma2(a2[t], w2.x, xv.x); fma2(a2[t], w2.y, xv.y);
            fma2(a3[t], w3.x, xv.x); fma2(a3[t], w3.y, xv.y);
        }
    }

    #pragma unroll
    for (int t = 0; t < TM; t++) {
        float v0 = hsum(a0[t]);
        float v1 = hsum(a1[t]);
        float v2 = hsum(a2[t]);
        float v3 = hsum(a3[t]);
        if (lane == t && t < rem) {
            float w = g_wass[slot0 + t];
            int tok = g_tok[slot0 + t];
            float* op = out + (size_t)tok * HID + row;
            atomicAdd(op + 0, v0 * w);
            atomicAdd(op + 1, v1 * w);
            atomicAdd(op + 2, v2 * w);
            atomicAdd(op + 3, v3 * w);
        }
    }
}

__global__ void __launch_bounds__(512, 1) down_k(const float* __restrict__ wd,
                                                 float* __restrict__ out)
{
    extern __shared__ ulonglong2 sh[];
    int e = blockIdx.y;
    int cnt = g_cnt[e];            // written by route_k (completed before gateup started)
    if (cnt == 0) { cudaGridDependencySynchronize(); return; }
    int base = g_off[e];
    int row0 = blockIdx.x * DN_ROWS_BLK;
    const float* wd_e = wd + (size_t)e * HID * INTER;

    uint32_t smem_u32 = (uint32_t)__cvta_generic_to_shared(sh);
    int warp = threadIdx.x >> 5;
    uint32_t wbase = smem_u32 + 67584 + warp * 8192;
    const ulonglong2* wsh = sh + DN_X_U2 + warp * 512;
    int row = row0 + warp * 4;

    auto issueP = [&](int g) {
        int lane = threadIdx.x & 31;
        const float* f0 = wd_e + (size_t)(row  ) * INTER + g * 128;
        const float* f1 = wd_e + (size_t)(row+1) * INTER + g * 128;
        const float* f2 = wd_e + (size_t)(row+2) * INTER + g * 128;
        const float* f3 = wd_e + (size_t)(row+3) * INTER + g * 128;
        uint32_t dst = wbase + (g & 3) * 2048;
        cpa16(dst +         lane*16, f0 + lane*4);
        cpa16(dst +  512 +  lane*16, f1 + lane*4);
        cpa16(dst + 1024 +  lane*16, f2 + lane*4);
        cpa16(dst + 1536 +  lane*16, f3 + lane*4);
    };

    bool first = true;
    for (int c0 = 0; c0 < cnt; c0 += 12) {
        int rem = cnt - c0; if (rem > 12) rem = 12;
        int tmv = rem + (rem & 1);
        __syncthreads();                        // prev consumers done with x
        for (int idx = rem * 352 + threadIdx.x; idx < tmv * 352; idx += 512) {
            ulonglong2 z; z.x = 0ull; z.y = 0ull; sh[idx] = z;
        }
        // weight prologue first (independent of gateup output)
        issueP(c0 == 0 ? 0 : 0); cpa_commit();  // g=0
        issueP(1); cpa_commit();
        issueP(2); cpa_commit();
        if (first) { cudaGridDependencySynchronize(); first = false; }
        // x tile (g_mixed) only after the dependency sync
        for (int idx = threadIdx.x; idx < rem * 352; idx += 512) {
            int slot = idx / 352, j = idx - slot * 352;
            cpa16(smem_u32 + idx * 16,
                  g_mixed + (size_t)(base + c0 + slot) * INTER + j * 4);
        }
        cpa_commit();
        switch (tmv) {
            case 2:  dn_all<2 >(wd_e, sh, wsh, wbase, row0, base + c0, rem, out); break;
            case 4:  dn_all<4 >(wd_e, sh, wsh, wbase, row0, base + c0, rem, out); break;
            case 6:  dn_all<6 >(wd_e, sh, wsh, wbase, row0, base + c0, rem, out); break;
            case 8:  dn_all<8 >(wd_e, sh, wsh, wbase, row0, base + c0, rem, out); break;
            case 10: dn_all<10>(wd_e, sh, wsh, wbase, row0, base + c0, rem, out); break;
            default: dn_all<12>(wd_e, sh, wsh, wbase, row0, base + c0, rem, out); break;
        }
    }
}

// ---------------- launch ----------------
extern "C" void kernel_launch(void* const* d_in, const int* in_sizes, int n_in,
                              void* d_out, int out_size)
{
    const float* x      = (const float*)d_in[0];
    const float* logits = (const float*)d_in[1];
    const float* wg     = (const float*)d_in[2];
    const float* wu     = (const float*)d_in[3];
    const float* wd     = (const float*)d_in[4];
    float* out = (float*)d_out;

    cudaFuncSetAttribute(gateup_k, cudaFuncAttributeMaxDynamicSharedMemorySize, GU_SMEM_B);
    cudaFuncSetAttribute(down_k,   cudaFuncAttributeMaxDynamicSharedMemorySize, DN_SMEM_B);

    route_k<<<1, 256>>>(logits);
    zero_k<<<(NTOK * HID) / 1024, 256>>>((float4*)out);
    gateup_k<<<dim3(GU_TILES, NEXP), 512, GU_SMEM_B>>>(x, wg, wu);

    // down_k overlaps gateup's tail via programmatic dependent launch
    cudaLaunchConfig_t cfg = {};
    cfg.gridDim = dim3(DN_TILES, NEXP);
    cfg.blockDim = dim3(512, 1, 1);
    cfg.dynamicSmemBytes = DN_SMEM_B;
    cfg.stream = 0;
    cudaLaunchAttribute attrs[1];
    attrs[0].id = cudaLaunchAttributeProgrammaticStreamSerialization;
    attrs[0].val.programmaticStreamSerializationAllowed = 1;
    cfg.attrs = attrs;
    cfg.numAttrs = 1;
    cudaLaunchKernelEx(&cfg, down_k, wd, out);
}